// round 15
// baseline (speedup 1.0000x reference)
#include <cuda_runtime.h>
#include <cuda_bf16.h>
#include <cstdint>

// Problem constants (fixed shapes from reference)
#define B_     4
#define NX_    400
#define NY_    200
#define NZ_    1
#define C_     256
#define NPRIME_ 173184                            // B*6*41*8*22
#define S_      (NX_ * NY_)                       // 80000
#define NVOX    (B_ * S_)                         // 320000

// Dual per-voxel point chains (one per channel-half block so each half can
// re-zero its own heads after reading -> no separate clear pass, no cross-
// block race). head: 0 = empty, else point_index+1. Zero at module load;
// each gather half-block re-zeroes the heads it consumed, so every graph
// replay starts clean. next arrays are fully rewritten before any read.
__device__ int g_headA[NVOX];
__device__ int g_headB[NVOX];
__device__ int g_nextA[NPRIME_];
__device__ int g_nextB[NPRIME_];

// ---------------------------------------------------------------------------
// Pass 1: build both per-voxel linked lists. ~7 MB traffic.
// (Exchange order may differ between A and B -> chains may order points
// differently; the summed point set per voxel is identical.)
// ---------------------------------------------------------------------------
__global__ __launch_bounds__(256) void build_chains(const int* __restrict__ geom)
{
    const int p = blockIdx.x * 256 + threadIdx.x;
    if (p >= NPRIME_) return;
    const int4 g = __ldg(reinterpret_cast<const int4*>(geom) + p);
    const int vox = (g.w * NX_ + g.x) * NY_ + g.y;   // gz==0 (NZ=1)
    g_nextA[p] = atomicExch(&g_headA[vox], p + 1);
    g_nextB[p] = atomicExch(&g_headB[vox], p + 1);
}

// ---------------------------------------------------------------------------
// Pass 2: gather + transpose. Block = 32 voxel rows x 128 channels
// (blockIdx.y selects the channel half and its private chain array).
// Tile 16 KB -> 8 blocks/SM (2048 threads). Warp g owns rows {8k+g}; its 4
// first chain steps issue as ONE batch (4x LDG.128 + 4x LDG.32 in flight,
// ~90% of points), rare tails walked sequentially. XOR-swizzled smem
// transpose emits each channel's 32 s-values as one full 128B output line
// via streaming stores (out is never re-read). Heads re-zeroed inline.
// ---------------------------------------------------------------------------
__global__ __launch_bounds__(256, 8) void gather_transpose_kernel(
    const float* __restrict__ x,
    float* __restrict__ out)
{
    __shared__ float4 tile4[32][32];          // [s-row][swizzled channel-quad]
    __shared__ int heads[32];

    const int blk  = blockIdx.x;              // 0 .. NVOX/32-1
    const int half = blockIdx.y;              // channel half: 0 or 1
    const int b    = blk / (S_ / 32);
    const int s0   = (blk % (S_ / 32)) * 32;
    const int tid  = threadIdx.x;

    int* __restrict__ headp = half ? g_headB : g_headA;
    const int* __restrict__ nextp = half ? g_nextB : g_nextA;

    if (tid < 32) {
        const int v = b * S_ + s0 + tid;
        heads[tid] = headp[v];
        headp[v] = 0;                         // re-arm own array for next replay
    }
    __syncthreads();

    const int g    = tid >> 5;                // warp id 0..7 -> rows 8k+g
    const int cq0  = tid & 31;                // channel quad within half
    const int qidx = half * 32 + cq0;         // float4 index into point row
    const float4 zero4 = make_float4(0.f, 0.f, 0.f, 0.f);

    int    h[4];
    int    nx[4];
    float4 acc[4];

    #pragma unroll
    for (int k = 0; k < 4; k++)
        h[k] = heads[8 * k + g];

    // Single batched first step: 8 independent loads in flight.
    #pragma unroll
    for (int k = 0; k < 4; k++) {
        if (h[k]) {
            nx[k]  = __ldg(nextp + (h[k] - 1));
            acc[k] = __ldcs(reinterpret_cast<const float4*>(
                                x + (size_t)(h[k] - 1) * C_) + qidx);
        } else {
            nx[k]  = 0;
            acc[k] = zero4;
        }
    }

    // Residual chain tails (rare; lambda = 0.54): sequential walk.
    #pragma unroll
    for (int k = 0; k < 4; k++) {
        int hh = nx[k];
        while (hh) {
            const float4 t = __ldcs(reinterpret_cast<const float4*>(
                                        x + (size_t)(hh - 1) * C_) + qidx);
            acc[k].x += t.x;
            acc[k].y += t.y;
            acc[k].z += t.z;
            acc[k].w += t.w;
            hh = __ldg(nextp + (hh - 1));
        }
    }

    // Stage to smem, XOR-swizzled: tile4[row][cq0 ^ (row>>2)].
    #pragma unroll
    for (int k = 0; k < 4; k++) {
        const int row = 8 * k + g;
        tile4[row][cq0 ^ (row >> 2)] = acc[k];
    }

    __syncthreads();

    // Store phase: warp w, lane l; q = l&7 (s-quad), cu = l>>3.
    // Iteration i: cq = w*4+i, channel c = 4*cq+cu. Reads tile4[4q+r][cq^q]
    // component cu -> bank-bijective over 32 lanes (conflict-free); each
    // STG.128 warp-phase fills 4 complete 128B output lines (streaming).
    const int w  = tid >> 5;
    const int l  = tid & 31;
    const int q  = l & 7;
    const int cu = l >> 3;

    float* dstb = out + (size_t)b * C_ * S_ + (size_t)(half * 128) * S_ + s0;

    #pragma unroll
    for (int i = 0; i < 4; i++) {
        const int cq = w * 4 + i;
        const int c  = 4 * cq + cu;
        float4 o;
        o.x = reinterpret_cast<const float*>(&tile4[4 * q + 0][cq ^ q])[cu];
        o.y = reinterpret_cast<const float*>(&tile4[4 * q + 1][cq ^ q])[cu];
        o.z = reinterpret_cast<const float*>(&tile4[4 * q + 2][cq ^ q])[cu];
        o.w = reinterpret_cast<const float*>(&tile4[4 * q + 3][cq ^ q])[cu];
        __stcs(reinterpret_cast<float4*>(dstb + (size_t)c * S_ + 4 * q), o);
    }
}

extern "C" void kernel_launch(void* const* d_in, const int* in_sizes, int n_in,
                              void* d_out, int out_size)
{
    const float* x    = (const float*)d_in[0];   // [NPRIME, C] float32
    const int*   geom = (const int*)  d_in[1];   // [NPRIME, 4] int32
    float*       out  = (float*)d_out;           // [B, C, NX, NY] float32

    build_chains<<<(NPRIME_ + 255) / 256, 256>>>(geom);

    dim3 grid(NVOX / 32, 2);
    gather_transpose_kernel<<<grid, 256>>>(x, out);
}